// round 15
// baseline (speedup 1.0000x reference)
#include <cuda_runtime.h>
#include <cstdint>

#define S_LEN   4096
#define NTASKS  256
#define NALGOS  64
#define WARM    192
#define CHUNK   256
#define NCHUNK  16
#define NCHAINS (NALGOS * NCHUNK)

// prep[s] = {tm[t_s][t_{s+1}]*wh1, tm[t_s][t_{s+2}]*wh2, wh3, tm[t_s][t_{s+3}]}
// (algo-independent; mem powers applied per algo inside the chain)
__device__ __align__(16) float4 prep_buf[S_LEN];
// handoff: per (a,chunk) k-values and res seed at the chunk seam
__device__ __align__(16) float k_glob[NCHAINS][CHUNK];
__device__ __align__(16) float seed_glob[NCHAINS][NTASKS];
__device__ int chain_done[NCHAINS];

__device__ __forceinline__ float rcpf(float x) {
    float y; asm("rcp.approx.f32 %0, %1;" : "=f"(y) : "f"(x)); return y;
}
__device__ __forceinline__ float tanhapx(float x) {
    float y; asm("tanh.approx.f32 %0, %1;" : "=f"(y) : "f"(x)); return y;
}
__device__ __forceinline__ float ldcgf(const float* p) {
    float v; asm volatile("ld.global.cg.f32 %0, [%1];" : "=f"(v) : "l"(p)); return v;
}

#define PACK64(u, lo, hi)   asm("mov.b64 %0, {%1, %2};" : "=l"(u) : "f"(lo), "f"(hi))
#define UNPACK64(lo, hi, u) asm("mov.b64 {%0, %1}, %2;" : "=f"(lo), "=f"(hi) : "l"(u))
#define MULX2(o, a, b)      asm("mul.rn.f32x2 %0, %1, %2;" : "=l"(o) : "l"(a), "l"(b))
#define FMAX2(o, a, b, c)   asm("fma.rn.f32x2 %0, %1, %2, %3;" : "=l"(o) : "l"(a), "l"(b), "l"(c))

// ---------------------------------------------------------------------------
// Prep: algo-independent coefficients, flag reset, output col-0 zeroing.
// ---------------------------------------------------------------------------
__global__ void __launch_bounds__(128) idl_prep(
    const int* __restrict__ lx, const float* __restrict__ tm,
    const float* __restrict__ diff, float* __restrict__ out)
{
    const int b = blockIdx.x;                      // 128 blocks
    if (b == 0) {
        for (int i = threadIdx.x; i < NCHAINS; i += 128)
            chain_done[i] = 0;
    }
    // zero output column 0 for all 64*256 rows
    const int idx = b * 128 + threadIdx.x;
    out[(size_t)idx * (size_t)(S_LEN + 1)] = 0.0f;

    if (b < 32) {
        const int s = b * 128 + threadIdx.x;
        const int t0 = __ldg(lx + s);
        const int t1 = __ldg(lx + min(s + 1, S_LEN - 1));
        const int t2 = __ldg(lx + min(s + 2, S_LEN - 1));
        const int t3 = __ldg(lx + min(s + 3, S_LEN - 1));

        const float wh1 = 0.5f * rcpf(__ldg(diff + t1));
        const float wh2 = 0.5f * rcpf(__ldg(diff + t2));
        const float wh3 = 0.5f * rcpf(__ldg(diff + t3));

        float4 o;
        o.x = __ldg(tm + t0 * NTASKS + t1) * wh1;
        o.y = __ldg(tm + t0 * NTASKS + t2) * wh2;
        o.z = wh3;
        o.w = __ldg(tm + t0 * NTASKS + t3);
        prep_buf[s] = o;
    }
}

// ---------------------------------------------------------------------------
// Chain: 64 blocks x 128 threads; each warp runs FOUR algos' k-chains for one
// chunk, sharing the tm row ring + prep coefficients (L2 row traffic / 4).
// PDL trigger at entry; releases 4 flags per warp on completion.
// ---------------------------------------------------------------------------
__global__ void __launch_bounds__(128) idl_chain(
    const int*   __restrict__ lx,
    const float* __restrict__ tm,
    const float* __restrict__ effA,
    const float* __restrict__ memA,
    const float* __restrict__ boostA)
{
    cudaTriggerProgrammaticLaunchCompletion();

    const int w    = threadIdx.x >> 5;
    const int lane = threadIdx.x & 31;
    const int gw   = blockIdx.x * 4 + w;          // 0..255
    const int a0   = (gw >> 4) << 2;              // algo quad base
    const int q    = gw & 15;

    float memv[4], effv[4], boostv[4], m2[4];
    uint64_t mm[4];
    #pragma unroll
    for (int j = 0; j < 4; j++) {
        memv[j]   = memA[a0 + j];
        effv[j]   = effA[a0 + j];
        boostv[j] = boostA[a0 + j];
        m2[j]     = memv[j] * memv[j];
        PACK64(mm[j], memv[j], memv[j]);
    }

    const int warm_n = q ? WARM : 0;
    const int s0     = q * CHUNK;
    const int s_base = s0 - warm_n;

    uint64_t R[4][4];                              // [algo][colpack] res state
    #pragma unroll
    for (int j = 0; j < 4; j++)
        #pragma unroll
        for (int c = 0; c < 4; c++) R[j][c] = 0;

    ulonglong2 rA[8], rB[8];                       // shared 8-deep row ring
    #pragma unroll
    for (int i = 0; i < 8; i++) {
        const int t = __ldg(lx + min(s_base + i, S_LEN - 1));
        const ulonglong2* rp = (const ulonglong2*)(tm + t * NTASKS + lane * 8);
        rA[i] = rp[0];
        rB[i] = rp[1];
    }
    float4 PF[4];                                  // prep ring depth 4
    #pragma unroll
    for (int i = 0; i < 4; i++)
        PF[i] = __ldg(prep_buf + min(s_base + i, S_LEN - 1));

    float g[4]   = {0.f, 0.f, 0.f, 0.f};
    float base[4] = {0.f, 0.f, 0.f, 0.f};
    float pb1[4]  = {0.f, 0.f, 0.f, 0.f};
    float Am[4]   = {0.f, 0.f, 0.f, 0.f};
    float kq[4][4];

    const int bq0 = a0 * NCHUNK + q;
    float* kout = k_glob[bq0];                     // algo j at offset j*NCHUNK*CHUNK

    // ---- warm region (no k output) ----
    for (int ib = 0; ib < warm_n; ib += 16) {
        #pragma unroll
        for (int u = 0; u < 16; u++) {
            const int s = s_base + ib + u;
            const float4 pf = PF[u & 3];

            uint64_t kk[4];
            #pragma unroll
            for (int j = 0; j < 4; j++) {
                float k   = fmaf(boostv[j], g[j], effv[j]);
                float arg = fmaf(k, pf.x, base[j]);
                g[j] = tanhapx(arg);
                base[j] = fmaf(k * memv[j], pf.y, pb1[j]);
                float in = fmaf(k, pf.w, Am[j]);
                pb1[j] = pf.z * (m2[j] * in);
                PACK64(kk[j], k, k);
            }

            const ulonglong2 ra = rA[u & 7];
            const ulonglong2 rb = rB[u & 7];
            #pragma unroll
            for (int j = 0; j < 4; j++) {
                uint64_t p;
                MULX2(p, ra.x, kk[j]); FMAX2(R[j][0], R[j][0], mm[j], p);
                MULX2(p, ra.y, kk[j]); FMAX2(R[j][1], R[j][1], mm[j], p);
                MULX2(p, rb.x, kk[j]); FMAX2(R[j][2], R[j][2], mm[j], p);
                MULX2(p, rb.y, kk[j]); FMAX2(R[j][3], R[j][3], mm[j], p);
            }

            const int cn = __ldg(lx + min(s + 4, S_LEN - 1));
            #pragma unroll
            for (int j = 0; j < 4; j++) {
                uint64_t sA = (cn & 2) ? R[j][1] : R[j][0];
                uint64_t sB = (cn & 2) ? R[j][3] : R[j][2];
                uint64_t sv = (cn & 4) ? sB : sA;
                float lo, hi; UNPACK64(lo, hi, sv);
                float v  = (cn & 1) ? hi : lo;
                float bc = __shfl_sync(0xffffffffu, v, cn >> 3);
                Am[j] = memv[j] * bc;
            }

            const int t8 = __ldg(lx + min(s + 8, S_LEN - 1));
            const ulonglong2* rp = (const ulonglong2*)(tm + t8 * NTASKS + lane * 8);
            rA[u & 7] = rp[0];
            rB[u & 7] = rp[1];
            PF[u & 3] = __ldg(prep_buf + min(s + 4, S_LEN - 1));
        }
    }

    // ---- dump res seeds (state after step s0-1; zeros for q==0) ----
    #pragma unroll
    for (int j = 0; j < 4; j++) {
        ulonglong2* rs = (ulonglong2*)&seed_glob[bq0 + j * NCHUNK][lane * 8];
        ulonglong2 d; d.x = R[j][0]; d.y = R[j][1]; rs[0] = d;
        d.x = R[j][2]; d.y = R[j][3]; rs[1] = d;
    }

    // ---- main region (emit k for all four algos) ----
    for (int ib = warm_n; ib < warm_n + CHUNK; ib += 16) {
        #pragma unroll
        for (int u = 0; u < 16; u++) {
            const int i = ib + u;
            const int s = s_base + i;
            const float4 pf = PF[u & 3];
            const int mi = i - warm_n;

            uint64_t kk[4];
            #pragma unroll
            for (int j = 0; j < 4; j++) {
                float k   = fmaf(boostv[j], g[j], effv[j]);
                float arg = fmaf(k, pf.x, base[j]);
                g[j] = tanhapx(arg);
                kq[j][u & 3] = k;
                base[j] = fmaf(k * memv[j], pf.y, pb1[j]);
                float in = fmaf(k, pf.w, Am[j]);
                pb1[j] = pf.z * (m2[j] * in);
                PACK64(kk[j], k, k);
            }

            if ((u & 3) == 3 && lane == 0) {
                #pragma unroll
                for (int j = 0; j < 4; j++)
                    *(float4*)(kout + j * (NCHUNK * CHUNK) + mi - 3) =
                        make_float4(kq[j][0], kq[j][1], kq[j][2], kq[j][3]);
            }

            const ulonglong2 ra = rA[u & 7];
            const ulonglong2 rb = rB[u & 7];
            #pragma unroll
            for (int j = 0; j < 4; j++) {
                uint64_t p;
                MULX2(p, ra.x, kk[j]); FMAX2(R[j][0], R[j][0], mm[j], p);
                MULX2(p, ra.y, kk[j]); FMAX2(R[j][1], R[j][1], mm[j], p);
                MULX2(p, rb.x, kk[j]); FMAX2(R[j][2], R[j][2], mm[j], p);
                MULX2(p, rb.y, kk[j]); FMAX2(R[j][3], R[j][3], mm[j], p);
            }

            const int cn = __ldg(lx + min(s + 4, S_LEN - 1));
            #pragma unroll
            for (int j = 0; j < 4; j++) {
                uint64_t sA = (cn & 2) ? R[j][1] : R[j][0];
                uint64_t sB = (cn & 2) ? R[j][3] : R[j][2];
                uint64_t sv = (cn & 4) ? sB : sA;
                float lo, hi; UNPACK64(lo, hi, sv);
                float v  = (cn & 1) ? hi : lo;
                float bc = __shfl_sync(0xffffffffu, v, cn >> 3);
                Am[j] = memv[j] * bc;
            }

            const int t8 = __ldg(lx + min(s + 8, S_LEN - 1));
            const ulonglong2* rp = (const ulonglong2*)(tm + t8 * NTASKS + lane * 8);
            rA[u & 7] = rp[0];
            rB[u & 7] = rp[1];
            PF[u & 3] = __ldg(prep_buf + min(s + 4, S_LEN - 1));
        }
    }

    // publish all four chunks
    __threadfence();
    __syncwarp();
    if (lane == 0) {
        #pragma unroll
        for (int j = 0; j < 4; j++)
            asm volatile("st.global.release.gpu.s32 [%0], %1;"
                         :: "l"(chain_done + bq0 + j * NCHUNK), "r"(1) : "memory");
    }
}

// ---------------------------------------------------------------------------
// Out (R14/R12 shape): 2048 blocks = 64 algos x 8 colgroups x 4 chunkgroups.
// One chunk per warp; tm slice staged during chain (PDL); acquire-spin.
// ---------------------------------------------------------------------------
__global__ void __launch_bounds__(128) idl_out(
    const int*   __restrict__ lx,
    const float* __restrict__ tm,
    const float* __restrict__ diff,
    const float* __restrict__ memA,
    float*       __restrict__ out)
{
    __shared__ float    tm_sh[NTASKS * 32];        // 32 KB: [t][c_local]
    __shared__ float    kf_sh[4][CHUNK];           // 4 KB
    __shared__ uint16_t t16_sh[4][CHUNK];          // 2 KB  (t*32)
    __shared__ float    sbuf[4][32][33];           // 16.9 KB

    const int b    = blockIdx.x;
    const int a    = b >> 5;
    const int rem  = b & 31;
    const int cg   = rem >> 2;          // colgroup 0..7 (32 cols each)
    const int cq   = rem & 3;           // chunkgroup 0..3
    const int tid  = threadIdx.x;
    const int w    = tid >> 5;
    const int lane = tid & 31;

    // stage tm column slice (input-only; overlaps chain via PDL)
    #pragma unroll
    for (int i = tid; i < NTASKS * 32; i += 128)
        tm_sh[i] = __ldg(tm + (i >> 5) * NTASKS + cg * 32 + (i & 31));
    __syncthreads();

    const int q  = cq * 4 + w;          // this warp's chunk
    const int s0 = q * CHUNK;
    const int bq = a * NCHUNK + q;

    // wait for this chunk's chain
    if (lane == 0) {
        int f;
        for (;;) {
            asm volatile("ld.global.acquire.gpu.s32 %0, [%1];"
                         : "=r"(f) : "l"(chain_done + bq) : "memory");
            if (f) break;
            __nanosleep(100);
        }
    }
    __syncwarp();

    // stage (t, k) stream
    for (int i = lane; i < CHUNK; i += 32) {
        kf_sh[w][i]  = ldcgf(&k_glob[bq][i]);
        t16_sh[w][i] = (uint16_t)(__ldg(lx + s0 + i) << 5);
    }
    __syncwarp();

    const int   col = cg * 32 + lane;
    const float mem = memA[a];
    const float wh  = 0.5f * rcpf(__ldg(diff + col));

    float r = ldcgf(&seed_glob[bq][col]);   // seeded: no warm-up

    float* outw = out + (size_t)(a * NTASKS + cg * 32) * (size_t)(S_LEN + 1)
                + 1 + s0 + lane;

    #pragma unroll 1
    for (int tile = 0; tile < CHUNK / 32; tile++) {
        #pragma unroll
        for (int j = 0; j < 32; j++) {
            const int idx = tile * 32 + j;
            const float tv = tm_sh[(int)t16_sh[w][idx] + lane];
            r = fmaf(r, mem, tv * kf_sh[w][idx]);
            sbuf[w][lane][j] = tanhapx(r * wh);
        }
        __syncwarp();
        const float* sb = &sbuf[w][0][lane];
        float* op = outw + tile * 32;
        #pragma unroll
        for (int cl = 0; cl < 32; cl++) {
            __stcs(op, *sb);
            op += (S_LEN + 1);
            sb += 33;
        }
        __syncwarp();
    }
}

extern "C" void kernel_launch(void* const* d_in, const int* in_sizes, int n_in,
                              void* d_out, int out_size)
{
    (void)in_sizes; (void)n_in; (void)out_size;
    const int*   lx    = (const int*)  d_in[0];
    const float* tm    = (const float*)d_in[1];
    const float* diff  = (const float*)d_in[2];
    const float* eff   = (const float*)d_in[3];
    const float* mem   = (const float*)d_in[4];
    const float* boost = (const float*)d_in[5];
    float*       out   = (float*)d_out;

    idl_prep<<<128, 128>>>(lx, tm, diff, out);
    idl_chain<<<NCHAINS / 4 / 4, 128>>>(lx, tm, eff, mem, boost);

    // PDL: idl_out may start while idl_chain runs (sync via chain_done flags)
    {
        cudaLaunchConfig_t cfg = {};
        cfg.gridDim  = dim3(NALGOS * 32, 1, 1);
        cfg.blockDim = dim3(128, 1, 1);
        cfg.dynamicSmemBytes = 0;
        cfg.stream = 0;
        cudaLaunchAttribute attr[1];
        attr[0].id = cudaLaunchAttributeProgrammaticStreamSerialization;
        attr[0].val.programmaticStreamSerializationAllowed = 1;
        cfg.attrs = attr;
        cfg.numAttrs = 1;
        cudaLaunchKernelEx(&cfg, idl_out, lx, tm, diff, mem, out);
    }
}

// round 16
// speedup vs baseline: 1.2306x; 1.2306x over previous
#include <cuda_runtime.h>
#include <cstdint>

#define S_LEN   4096
#define NTASKS  256
#define NALGOS  64
#define WARM    128
#define CHUNK   256
#define NCHUNK  16
#define NCHAINS (NALGOS * NCHUNK)

// prep[s] = {tm[t_s][t_{s+1}]*wh1, tm[t_s][t_{s+2}]*wh2, wh3, tm[t_s][t_{s+3}]}
// (algo-independent; mem powers applied per algo inside the chain)
__device__ __align__(16) float4 prep_buf[S_LEN];
// handoff: per (a,chunk) k-values and res seed at the chunk seam
__device__ __align__(16) float k_glob[NCHAINS][CHUNK];
__device__ __align__(16) float seed_glob[NCHAINS][NTASKS];
__device__ int chain_done[NCHAINS];

__device__ __forceinline__ float rcpf(float x) {
    float y; asm("rcp.approx.f32 %0, %1;" : "=f"(y) : "f"(x)); return y;
}
__device__ __forceinline__ float tanhapx(float x) {
    float y; asm("tanh.approx.f32 %0, %1;" : "=f"(y) : "f"(x)); return y;
}
__device__ __forceinline__ float ldcgf(const float* p) {
    float v; asm volatile("ld.global.cg.f32 %0, [%1];" : "=f"(v) : "l"(p)); return v;
}

#define PACK64(u, lo, hi)   asm("mov.b64 %0, {%1, %2};" : "=l"(u) : "f"(lo), "f"(hi))
#define UNPACK64(lo, hi, u) asm("mov.b64 {%0, %1}, %2;" : "=f"(lo), "=f"(hi) : "l"(u))
#define MULX2(o, a, b)      asm("mul.rn.f32x2 %0, %1, %2;" : "=l"(o) : "l"(a), "l"(b))
#define FMAX2(o, a, b, c)   asm("fma.rn.f32x2 %0, %1, %2, %3;" : "=l"(o) : "l"(a), "l"(b), "l"(c))

// ---------------------------------------------------------------------------
// Prep: algo-independent coefficients, flag reset, output col-0 zeroing.
// ---------------------------------------------------------------------------
__global__ void __launch_bounds__(128) idl_prep(
    const int* __restrict__ lx, const float* __restrict__ tm,
    const float* __restrict__ diff, float* __restrict__ out)
{
    const int b = blockIdx.x;                      // 128 blocks
    if (b == 0) {
        for (int i = threadIdx.x; i < NCHAINS; i += 128)
            chain_done[i] = 0;
    }
    // zero output column 0 for all 64*256 rows
    const int idx = b * 128 + threadIdx.x;
    out[(size_t)idx * (size_t)(S_LEN + 1)] = 0.0f;

    if (b < 32) {
        const int s = b * 128 + threadIdx.x;
        const int t0 = __ldg(lx + s);
        const int t1 = __ldg(lx + min(s + 1, S_LEN - 1));
        const int t2 = __ldg(lx + min(s + 2, S_LEN - 1));
        const int t3 = __ldg(lx + min(s + 3, S_LEN - 1));

        const float wh1 = 0.5f * rcpf(__ldg(diff + t1));
        const float wh2 = 0.5f * rcpf(__ldg(diff + t2));
        const float wh3 = 0.5f * rcpf(__ldg(diff + t3));

        float4 o;
        o.x = __ldg(tm + t0 * NTASKS + t1) * wh1;
        o.y = __ldg(tm + t0 * NTASKS + t2) * wh2;
        o.z = wh3;
        o.w = __ldg(tm + t0 * NTASKS + t3);
        prep_buf[s] = o;
    }
}

// ---------------------------------------------------------------------------
// Chain: 128 blocks x 128 threads; each warp runs TWO algos' k-chains for one
// chunk, sharing the tm row ring + prep coefficients (L2 row traffic / 2).
// Separate warm/main loops. PDL trigger at entry.
// ---------------------------------------------------------------------------
__global__ void __launch_bounds__(128) idl_chain(
    const int*   __restrict__ lx,
    const float* __restrict__ tm,
    const float* __restrict__ effA,
    const float* __restrict__ memA,
    const float* __restrict__ boostA)
{
    cudaTriggerProgrammaticLaunchCompletion();

    const int w    = threadIdx.x >> 5;
    const int lane = threadIdx.x & 31;
    const int gw   = blockIdx.x * 4 + w;          // 0..511
    const int a0   = (gw >> 4) * 2;               // algo pair base
    const int q    = gw & 15;

    const float mem0 = memA[a0],     eff0 = effA[a0],     boost0 = boostA[a0];
    const float mem1 = memA[a0 + 1], eff1 = effA[a0 + 1], boost1 = boostA[a0 + 1];
    const float m20 = mem0 * mem0, m21 = mem1 * mem1;

    const int warm_n = q ? WARM : 0;
    const int s0     = q * CHUNK;
    const int s_base = s0 - warm_n;

    uint64_t u00 = 0, u01 = 0, u02 = 0, u03 = 0;   // algo0 res, cols lane*8+0..7
    uint64_t u10 = 0, u11 = 0, u12 = 0, u13 = 0;   // algo1 res
    uint64_t mm0; PACK64(mm0, mem0, mem0);
    uint64_t mm1; PACK64(mm1, mem1, mem1);

    ulonglong2 rA[8], rB[8];                       // shared 8-deep row ring
    #pragma unroll
    for (int i = 0; i < 8; i++) {
        const int t = __ldg(lx + min(s_base + i, S_LEN - 1));
        const ulonglong2* rp = (const ulonglong2*)(tm + t * NTASKS + lane * 8);
        rA[i] = rp[0];
        rB[i] = rp[1];
    }
    float4 PF[8];
    #pragma unroll
    for (int i = 0; i < 8; i++)
        PF[i] = __ldg(prep_buf + min(s_base + i, S_LEN - 1));

    float g0 = 0.f, base0 = 0.f, pb10 = 0.f, Am0 = 0.f;
    float g1 = 0.f, base1 = 0.f, pb11 = 0.f, Am1 = 0.f;
    float kq0[4], kq1[4];

    const int bq0 = a0 * NCHUNK + q;
    const int bq1 = bq0 + NCHUNK;

    // ---- warm region (no k output) ----
    for (int ib = 0; ib < warm_n; ib += 16) {
        #pragma unroll
        for (int u = 0; u < 16; u++) {
            const int s = s_base + ib + u;
            const float4 pf = PF[u & 7];

            float k0   = fmaf(boost0, g0, eff0);
            float k1   = fmaf(boost1, g1, eff1);
            float arg0 = fmaf(k0, pf.x, base0);
            float arg1 = fmaf(k1, pf.x, base1);
            g0 = tanhapx(arg0);
            g1 = tanhapx(arg1);

            base0 = fmaf(k0 * mem0, pf.y, pb10);
            base1 = fmaf(k1 * mem1, pf.y, pb11);
            float in0 = fmaf(k0, pf.w, Am0);
            float in1 = fmaf(k1, pf.w, Am1);
            pb10 = pf.z * (m20 * in0);
            pb11 = pf.z * (m21 * in1);

            uint64_t kk0; PACK64(kk0, k0, k0);
            uint64_t kk1; PACK64(kk1, k1, k1);
            const ulonglong2 ra = rA[u & 7];
            const ulonglong2 rb = rB[u & 7];
            uint64_t p;
            MULX2(p, ra.x, kk0); FMAX2(u00, u00, mm0, p);
            MULX2(p, ra.y, kk0); FMAX2(u01, u01, mm0, p);
            MULX2(p, rb.x, kk0); FMAX2(u02, u02, mm0, p);
            MULX2(p, rb.y, kk0); FMAX2(u03, u03, mm0, p);
            MULX2(p, ra.x, kk1); FMAX2(u10, u10, mm1, p);
            MULX2(p, ra.y, kk1); FMAX2(u11, u11, mm1, p);
            MULX2(p, rb.x, kk1); FMAX2(u12, u12, mm1, p);
            MULX2(p, rb.y, kk1); FMAX2(u13, u13, mm1, p);

            const int cn = __ldg(lx + min(s + 4, S_LEN - 1));
            {
                uint64_t sA = (cn & 2) ? u01 : u00;
                uint64_t sB = (cn & 2) ? u03 : u02;
                uint64_t sv = (cn & 4) ? sB : sA;
                float lo, hi; UNPACK64(lo, hi, sv);
                float v  = (cn & 1) ? hi : lo;
                float bc = __shfl_sync(0xffffffffu, v, cn >> 3);
                Am0 = mem0 * bc;
            }
            {
                uint64_t sA = (cn & 2) ? u11 : u10;
                uint64_t sB = (cn & 2) ? u13 : u12;
                uint64_t sv = (cn & 4) ? sB : sA;
                float lo, hi; UNPACK64(lo, hi, sv);
                float v  = (cn & 1) ? hi : lo;
                float bc = __shfl_sync(0xffffffffu, v, cn >> 3);
                Am1 = mem1 * bc;
            }

            const int t8 = __ldg(lx + min(s + 8, S_LEN - 1));
            const ulonglong2* rp = (const ulonglong2*)(tm + t8 * NTASKS + lane * 8);
            rA[u & 7] = rp[0];
            rB[u & 7] = rp[1];
            PF[u & 7] = __ldg(prep_buf + min(s + 8, S_LEN - 1));
        }
    }

    // ---- dump res seeds (state after step s0-1; zeros for q==0) ----
    {
        ulonglong2* rs0 = (ulonglong2*)&seed_glob[bq0][lane * 8];
        ulonglong2 d; d.x = u00; d.y = u01; rs0[0] = d;
        d.x = u02; d.y = u03; rs0[1] = d;
        ulonglong2* rs1 = (ulonglong2*)&seed_glob[bq1][lane * 8];
        d.x = u10; d.y = u11; rs1[0] = d;
        d.x = u12; d.y = u13; rs1[1] = d;
    }

    // ---- main region (emit k for both algos) ----
    float* kout0 = k_glob[bq0];
    float* kout1 = k_glob[bq1];
    for (int ib = warm_n; ib < warm_n + CHUNK; ib += 16) {
        #pragma unroll
        for (int u = 0; u < 16; u++) {
            const int i = ib + u;
            const int s = s_base + i;
            const float4 pf = PF[u & 7];

            float k0   = fmaf(boost0, g0, eff0);
            float k1   = fmaf(boost1, g1, eff1);
            float arg0 = fmaf(k0, pf.x, base0);
            float arg1 = fmaf(k1, pf.x, base1);
            g0 = tanhapx(arg0);
            g1 = tanhapx(arg1);

            const int mi = i - warm_n;
            kq0[u & 3] = k0;
            kq1[u & 3] = k1;
            if ((u & 3) == 3 && lane == 0) {
                *(float4*)(kout0 + mi - 3) = make_float4(kq0[0], kq0[1], kq0[2], kq0[3]);
                *(float4*)(kout1 + mi - 3) = make_float4(kq1[0], kq1[1], kq1[2], kq1[3]);
            }

            base0 = fmaf(k0 * mem0, pf.y, pb10);
            base1 = fmaf(k1 * mem1, pf.y, pb11);
            float in0 = fmaf(k0, pf.w, Am0);
            float in1 = fmaf(k1, pf.w, Am1);
            pb10 = pf.z * (m20 * in0);
            pb11 = pf.z * (m21 * in1);

            uint64_t kk0; PACK64(kk0, k0, k0);
            uint64_t kk1; PACK64(kk1, k1, k1);
            const ulonglong2 ra = rA[u & 7];
            const ulonglong2 rb = rB[u & 7];
            uint64_t p;
            MULX2(p, ra.x, kk0); FMAX2(u00, u00, mm0, p);
            MULX2(p, ra.y, kk0); FMAX2(u01, u01, mm0, p);
            MULX2(p, rb.x, kk0); FMAX2(u02, u02, mm0, p);
            MULX2(p, rb.y, kk0); FMAX2(u03, u03, mm0, p);
            MULX2(p, ra.x, kk1); FMAX2(u10, u10, mm1, p);
            MULX2(p, ra.y, kk1); FMAX2(u11, u11, mm1, p);
            MULX2(p, rb.x, kk1); FMAX2(u12, u12, mm1, p);
            MULX2(p, rb.y, kk1); FMAX2(u13, u13, mm1, p);

            const int cn = __ldg(lx + min(s + 4, S_LEN - 1));
            {
                uint64_t sA = (cn & 2) ? u01 : u00;
                uint64_t sB = (cn & 2) ? u03 : u02;
                uint64_t sv = (cn & 4) ? sB : sA;
                float lo, hi; UNPACK64(lo, hi, sv);
                float v  = (cn & 1) ? hi : lo;
                float bc = __shfl_sync(0xffffffffu, v, cn >> 3);
                Am0 = mem0 * bc;
            }
            {
                uint64_t sA = (cn & 2) ? u11 : u10;
                uint64_t sB = (cn & 2) ? u13 : u12;
                uint64_t sv = (cn & 4) ? sB : sA;
                float lo, hi; UNPACK64(lo, hi, sv);
                float v  = (cn & 1) ? hi : lo;
                float bc = __shfl_sync(0xffffffffu, v, cn >> 3);
                Am1 = mem1 * bc;
            }

            const int t8 = __ldg(lx + min(s + 8, S_LEN - 1));
            const ulonglong2* rp = (const ulonglong2*)(tm + t8 * NTASKS + lane * 8);
            rA[u & 7] = rp[0];
            rB[u & 7] = rp[1];
            PF[u & 7] = __ldg(prep_buf + min(s + 8, S_LEN - 1));
        }
    }

    // publish both chunks
    __threadfence();
    __syncwarp();
    if (lane == 0) {
        asm volatile("st.global.release.gpu.s32 [%0], %1;"
                     :: "l"(chain_done + bq0), "r"(1) : "memory");
        asm volatile("st.global.release.gpu.s32 [%0], %1;"
                     :: "l"(chain_done + bq1), "r"(1) : "memory");
    }
}

// ---------------------------------------------------------------------------
// Out (R12/R14 shape): 2048 blocks = 64 algos x 8 colgroups x 4 chunkgroups.
// One chunk per warp; tm slice staged during chain (PDL); acquire-spin.
// ---------------------------------------------------------------------------
__global__ void __launch_bounds__(128) idl_out(
    const int*   __restrict__ lx,
    const float* __restrict__ tm,
    const float* __restrict__ diff,
    const float* __restrict__ memA,
    float*       __restrict__ out)
{
    __shared__ float    tm_sh[NTASKS * 32];        // 32 KB: [t][c_local]
    __shared__ float    kf_sh[4][CHUNK];           // 4 KB
    __shared__ uint16_t t16_sh[4][CHUNK];          // 2 KB  (t*32)
    __shared__ float    sbuf[4][32][33];           // 16.9 KB

    const int b    = blockIdx.x;
    const int a    = b >> 5;
    const int rem  = b & 31;
    const int cg   = rem >> 2;          // colgroup 0..7 (32 cols each)
    const int cq   = rem & 3;           // chunkgroup 0..3
    const int tid  = threadIdx.x;
    const int w    = tid >> 5;
    const int lane = tid & 31;

    // stage tm column slice (input-only; overlaps chain via PDL)
    #pragma unroll
    for (int i = tid; i < NTASKS * 32; i += 128)
        tm_sh[i] = __ldg(tm + (i >> 5) * NTASKS + cg * 32 + (i & 31));
    __syncthreads();

    const int q  = cq * 4 + w;          // this warp's chunk
    const int s0 = q * CHUNK;
    const int bq = a * NCHUNK + q;

    // wait for this chunk's chain
    if (lane == 0) {
        int f;
        for (;;) {
            asm volatile("ld.global.acquire.gpu.s32 %0, [%1];"
                         : "=r"(f) : "l"(chain_done + bq) : "memory");
            if (f) break;
            __nanosleep(100);
        }
    }
    __syncwarp();

    // stage (t, k) stream
    for (int i = lane; i < CHUNK; i += 32) {
        kf_sh[w][i]  = ldcgf(&k_glob[bq][i]);
        t16_sh[w][i] = (uint16_t)(__ldg(lx + s0 + i) << 5);
    }
    __syncwarp();

    const int   col = cg * 32 + lane;
    const float mem = memA[a];
    const float wh  = 0.5f * rcpf(__ldg(diff + col));

    float r = ldcgf(&seed_glob[bq][col]);   // seeded: no warm-up

    float* outw = out + (size_t)(a * NTASKS + cg * 32) * (size_t)(S_LEN + 1)
                + 1 + s0 + lane;

    #pragma unroll 1
    for (int tile = 0; tile < CHUNK / 32; tile++) {
        #pragma unroll
        for (int j = 0; j < 32; j++) {
            const int idx = tile * 32 + j;
            const float tv = tm_sh[(int)t16_sh[w][idx] + lane];
            r = fmaf(r, mem, tv * kf_sh[w][idx]);
            sbuf[w][lane][j] = tanhapx(r * wh);
        }
        __syncwarp();
        const float* sb = &sbuf[w][0][lane];
        float* op = outw + tile * 32;
        #pragma unroll
        for (int cl = 0; cl < 32; cl++) {
            __stcs(op, *sb);
            op += (S_LEN + 1);
            sb += 33;
        }
        __syncwarp();
    }
}

extern "C" void kernel_launch(void* const* d_in, const int* in_sizes, int n_in,
                              void* d_out, int out_size)
{
    (void)in_sizes; (void)n_in; (void)out_size;
    const int*   lx    = (const int*)  d_in[0];
    const float* tm    = (const float*)d_in[1];
    const float* diff  = (const float*)d_in[2];
    const float* eff   = (const float*)d_in[3];
    const float* mem   = (const float*)d_in[4];
    const float* boost = (const float*)d_in[5];
    float*       out   = (float*)d_out;

    idl_prep<<<128, 128>>>(lx, tm, diff, out);
    idl_chain<<<NCHAINS / 2 / 4, 128>>>(lx, tm, eff, mem, boost);

    // PDL: idl_out may start while idl_chain runs (sync via chain_done flags)
    {
        cudaLaunchConfig_t cfg = {};
        cfg.gridDim  = dim3(NALGOS * 32, 1, 1);
        cfg.blockDim = dim3(128, 1, 1);
        cfg.dynamicSmemBytes = 0;
        cfg.stream = 0;
        cudaLaunchAttribute attr[1];
        attr[0].id = cudaLaunchAttributeProgrammaticStreamSerialization;
        attr[0].val.programmaticStreamSerializationAllowed = 1;
        cfg.attrs = attr;
        cfg.numAttrs = 1;
        cudaLaunchKernelEx(&cfg, idl_out, lx, tm, diff, mem, out);
    }
}

// round 17
// speedup vs baseline: 1.2742x; 1.0355x over previous
#include <cuda_runtime.h>
#include <cstdint>

#define S_LEN   4096
#define NTASKS  256
#define NALGOS  64
#define WARM    96
#define CHUNK   256
#define NCHUNK  16
#define NCHAINS (NALGOS * NCHUNK)
#define NE      368     // per-warp coefficient window (WARM+CHUNK+8 rounded up)

// handoff: per (a,chunk) k-values and res seed at the chunk seam
__device__ __align__(16) float k_glob[NCHAINS][CHUNK];
__device__ __align__(16) float seed_glob[NCHAINS][NTASKS];
// semaphore: chain sets 8; each of the 8 consumer blocks decrements once -> 0
__device__ int chain_done[NCHAINS];

__device__ __forceinline__ float rcpf(float x) {
    float y; asm("rcp.approx.f32 %0, %1;" : "=f"(y) : "f"(x)); return y;
}
__device__ __forceinline__ float tanhapx(float x) {
    float y; asm("tanh.approx.f32 %0, %1;" : "=f"(y) : "f"(x)); return y;
}
__device__ __forceinline__ float ldcgf(const float* p) {
    float v; asm volatile("ld.global.cg.f32 %0, [%1];" : "=f"(v) : "l"(p)); return v;
}

#define PACK64(u, lo, hi)   asm("mov.b64 %0, {%1, %2};" : "=l"(u) : "f"(lo), "f"(hi))
#define UNPACK64(lo, hi, u) asm("mov.b64 {%0, %1}, %2;" : "=f"(lo), "=f"(hi) : "l"(u))
#define MULX2(o, a, b)      asm("mul.rn.f32x2 %0, %1, %2;" : "=l"(o) : "l"(a), "l"(b))
#define FMAX2(o, a, b, c)   asm("fma.rn.f32x2 %0, %1, %2, %3;" : "=l"(o) : "l"(a), "l"(b), "l"(c))

// ---------------------------------------------------------------------------
// Chain: 128 blocks x 128 threads; each warp runs TWO algos' k-chains for one
// chunk, sharing the tm row ring. Coefficients (prep) computed INLINE into
// smem at warp start (no prep kernel, no prep_buf). PDL trigger at entry.
// Releases chain_done[bq] = 8 (consumer count) when the chunk is published.
// ---------------------------------------------------------------------------
__global__ void __launch_bounds__(128) idl_chain(
    const int*   __restrict__ lx,
    const float* __restrict__ tm,
    const float* __restrict__ diff,
    const float* __restrict__ effA,
    const float* __restrict__ memA,
    const float* __restrict__ boostA)
{
    cudaTriggerProgrammaticLaunchCompletion();

    __shared__ __align__(16) float4 pf_sh[4][NE];   // 23.5 KB
    __shared__ int                  t_sh[4][NE];    // 5.9 KB

    const int w    = threadIdx.x >> 5;
    const int lane = threadIdx.x & 31;
    const int gw   = blockIdx.x * 4 + w;          // 0..511
    const int a0   = (gw >> 4) * 2;               // algo pair base
    const int q    = gw & 15;

    const float mem0 = memA[a0],     eff0 = effA[a0],     boost0 = boostA[a0];
    const float mem1 = memA[a0 + 1], eff1 = effA[a0 + 1], boost1 = boostA[a0 + 1];
    const float m20 = mem0 * mem0, m21 = mem1 * mem1;

    const int warm_n = q ? WARM : 0;
    const int s0     = q * CHUNK;
    const int s_base = s0 - warm_n;

    // ---- inline prep: coefficient + t window for this warp's s-range ----
    // pf_sh[e] = {tm[t_s][t_{s+1}]*wh1, tm[t_s][t_{s+2}]*wh2, wh3, tm[t_s][t_{s+3}]}
    #pragma unroll 4
    for (int e = lane; e < NE; e += 32) {
        const int s  = min(s_base + e, S_LEN - 1);
        const int t0 = __ldg(lx + s);
        const int t1 = __ldg(lx + min(s + 1, S_LEN - 1));
        const int t2 = __ldg(lx + min(s + 2, S_LEN - 1));
        const int t3 = __ldg(lx + min(s + 3, S_LEN - 1));
        const float wh1 = 0.5f * rcpf(__ldg(diff + t1));
        const float wh2 = 0.5f * rcpf(__ldg(diff + t2));
        const float wh3 = 0.5f * rcpf(__ldg(diff + t3));
        float4 o;
        o.x = __ldg(tm + t0 * NTASKS + t1) * wh1;
        o.y = __ldg(tm + t0 * NTASKS + t2) * wh2;
        o.z = wh3;
        o.w = __ldg(tm + t0 * NTASKS + t3);
        pf_sh[w][e] = o;
        t_sh[w][e]  = t0;
    }
    __syncwarp();

    uint64_t u00 = 0, u01 = 0, u02 = 0, u03 = 0;   // algo0 res, cols lane*8+0..7
    uint64_t u10 = 0, u11 = 0, u12 = 0, u13 = 0;   // algo1 res
    uint64_t mm0; PACK64(mm0, mem0, mem0);
    uint64_t mm1; PACK64(mm1, mem1, mem1);

    ulonglong2 rA[8], rB[8];                       // shared 8-deep row ring
    #pragma unroll
    for (int i = 0; i < 8; i++) {
        const int t = t_sh[w][i];
        const ulonglong2* rp = (const ulonglong2*)(tm + t * NTASKS + lane * 8);
        rA[i] = rp[0];
        rB[i] = rp[1];
    }

    float g0 = 0.f, base0 = 0.f, pb10 = 0.f, Am0 = 0.f;
    float g1 = 0.f, base1 = 0.f, pb11 = 0.f, Am1 = 0.f;
    float kq0[4], kq1[4];

    const int bq0 = a0 * NCHUNK + q;
    const int bq1 = bq0 + NCHUNK;

    // ---- warm region (no k output) ----
    for (int ib = 0; ib < warm_n; ib += 16) {
        #pragma unroll
        for (int u = 0; u < 16; u++) {
            const int i = ib + u;
            const float4 pf = pf_sh[w][i];

            float k0   = fmaf(boost0, g0, eff0);
            float k1   = fmaf(boost1, g1, eff1);
            float arg0 = fmaf(k0, pf.x, base0);
            float arg1 = fmaf(k1, pf.x, base1);
            g0 = tanhapx(arg0);
            g1 = tanhapx(arg1);

            base0 = fmaf(k0 * mem0, pf.y, pb10);
            base1 = fmaf(k1 * mem1, pf.y, pb11);
            float in0 = fmaf(k0, pf.w, Am0);
            float in1 = fmaf(k1, pf.w, Am1);
            pb10 = pf.z * (m20 * in0);
            pb11 = pf.z * (m21 * in1);

            uint64_t kk0; PACK64(kk0, k0, k0);
            uint64_t kk1; PACK64(kk1, k1, k1);
            const ulonglong2 ra = rA[u & 7];
            const ulonglong2 rb = rB[u & 7];
            uint64_t p;
            MULX2(p, ra.x, kk0); FMAX2(u00, u00, mm0, p);
            MULX2(p, ra.y, kk0); FMAX2(u01, u01, mm0, p);
            MULX2(p, rb.x, kk0); FMAX2(u02, u02, mm0, p);
            MULX2(p, rb.y, kk0); FMAX2(u03, u03, mm0, p);
            MULX2(p, ra.x, kk1); FMAX2(u10, u10, mm1, p);
            MULX2(p, ra.y, kk1); FMAX2(u11, u11, mm1, p);
            MULX2(p, rb.x, kk1); FMAX2(u12, u12, mm1, p);
            MULX2(p, rb.y, kk1); FMAX2(u13, u13, mm1, p);

            const int cn = t_sh[w][i + 4];
            {
                uint64_t sA = (cn & 2) ? u01 : u00;
                uint64_t sB = (cn & 2) ? u03 : u02;
                uint64_t sv = (cn & 4) ? sB : sA;
                float lo, hi; UNPACK64(lo, hi, sv);
                float v  = (cn & 1) ? hi : lo;
                float bc = __shfl_sync(0xffffffffu, v, cn >> 3);
                Am0 = mem0 * bc;
            }
            {
                uint64_t sA = (cn & 2) ? u11 : u10;
                uint64_t sB = (cn & 2) ? u13 : u12;
                uint64_t sv = (cn & 4) ? sB : sA;
                float lo, hi; UNPACK64(lo, hi, sv);
                float v  = (cn & 1) ? hi : lo;
                float bc = __shfl_sync(0xffffffffu, v, cn >> 3);
                Am1 = mem1 * bc;
            }

            const int t8 = t_sh[w][i + 8];
            const ulonglong2* rp = (const ulonglong2*)(tm + t8 * NTASKS + lane * 8);
            rA[u & 7] = rp[0];
            rB[u & 7] = rp[1];
        }
    }

    // ---- dump res seeds (state after step s0-1; zeros for q==0) ----
    {
        ulonglong2* rs0 = (ulonglong2*)&seed_glob[bq0][lane * 8];
        ulonglong2 d; d.x = u00; d.y = u01; rs0[0] = d;
        d.x = u02; d.y = u03; rs0[1] = d;
        ulonglong2* rs1 = (ulonglong2*)&seed_glob[bq1][lane * 8];
        d.x = u10; d.y = u11; rs1[0] = d;
        d.x = u12; d.y = u13; rs1[1] = d;
    }

    // ---- main region (emit k for both algos) ----
    float* kout0 = k_glob[bq0];
    float* kout1 = k_glob[bq1];
    for (int ib = warm_n; ib < warm_n + CHUNK; ib += 16) {
        #pragma unroll
        for (int u = 0; u < 16; u++) {
            const int i = ib + u;
            const float4 pf = pf_sh[w][i];

            float k0   = fmaf(boost0, g0, eff0);
            float k1   = fmaf(boost1, g1, eff1);
            float arg0 = fmaf(k0, pf.x, base0);
            float arg1 = fmaf(k1, pf.x, base1);
            g0 = tanhapx(arg0);
            g1 = tanhapx(arg1);

            const int mi = i - warm_n;
            kq0[u & 3] = k0;
            kq1[u & 3] = k1;
            if ((u & 3) == 3 && lane == 0) {
                *(float4*)(kout0 + mi - 3) = make_float4(kq0[0], kq0[1], kq0[2], kq0[3]);
                *(float4*)(kout1 + mi - 3) = make_float4(kq1[0], kq1[1], kq1[2], kq1[3]);
            }

            base0 = fmaf(k0 * mem0, pf.y, pb10);
            base1 = fmaf(k1 * mem1, pf.y, pb11);
            float in0 = fmaf(k0, pf.w, Am0);
            float in1 = fmaf(k1, pf.w, Am1);
            pb10 = pf.z * (m20 * in0);
            pb11 = pf.z * (m21 * in1);

            uint64_t kk0; PACK64(kk0, k0, k0);
            uint64_t kk1; PACK64(kk1, k1, k1);
            const ulonglong2 ra = rA[u & 7];
            const ulonglong2 rb = rB[u & 7];
            uint64_t p;
            MULX2(p, ra.x, kk0); FMAX2(u00, u00, mm0, p);
            MULX2(p, ra.y, kk0); FMAX2(u01, u01, mm0, p);
            MULX2(p, rb.x, kk0); FMAX2(u02, u02, mm0, p);
            MULX2(p, rb.y, kk0); FMAX2(u03, u03, mm0, p);
            MULX2(p, ra.x, kk1); FMAX2(u10, u10, mm1, p);
            MULX2(p, ra.y, kk1); FMAX2(u11, u11, mm1, p);
            MULX2(p, rb.x, kk1); FMAX2(u12, u12, mm1, p);
            MULX2(p, rb.y, kk1); FMAX2(u13, u13, mm1, p);

            const int cn = t_sh[w][i + 4];
            {
                uint64_t sA = (cn & 2) ? u01 : u00;
                uint64_t sB = (cn & 2) ? u03 : u02;
                uint64_t sv = (cn & 4) ? sB : sA;
                float lo, hi; UNPACK64(lo, hi, sv);
                float v  = (cn & 1) ? hi : lo;
                float bc = __shfl_sync(0xffffffffu, v, cn >> 3);
                Am0 = mem0 * bc;
            }
            {
                uint64_t sA = (cn & 2) ? u11 : u10;
                uint64_t sB = (cn & 2) ? u13 : u12;
                uint64_t sv = (cn & 4) ? sB : sA;
                float lo, hi; UNPACK64(lo, hi, sv);
                float v  = (cn & 1) ? hi : lo;
                float bc = __shfl_sync(0xffffffffu, v, cn >> 3);
                Am1 = mem1 * bc;
            }

            const int t8 = t_sh[w][i + 8];
            const ulonglong2* rp = (const ulonglong2*)(tm + t8 * NTASKS + lane * 8);
            rA[u & 7] = rp[0];
            rB[u & 7] = rp[1];
        }
    }

    // publish both chunks: release with consumer count (8 colgroup blocks each)
    __threadfence();
    __syncwarp();
    if (lane == 0) {
        asm volatile("st.global.release.gpu.s32 [%0], %1;"
                     :: "l"(chain_done + bq0), "r"(8) : "memory");
        asm volatile("st.global.release.gpu.s32 [%0], %1;"
                     :: "l"(chain_done + bq1), "r"(8) : "memory");
    }
}

// ---------------------------------------------------------------------------
// Out: 2048 blocks = 64 algos x 8 colgroups x 4 chunkgroups. One chunk per
// warp; tm slice staged during chain (PDL); acquire-spin on the semaphore,
// then decrement it once (returns to 0 for the next graph replay).
// ---------------------------------------------------------------------------
__global__ void __launch_bounds__(128) idl_out(
    const int*   __restrict__ lx,
    const float* __restrict__ tm,
    const float* __restrict__ diff,
    const float* __restrict__ memA,
    float*       __restrict__ out)
{
    __shared__ float    tm_sh[NTASKS * 32];        // 32 KB: [t][c_local]
    __shared__ float    kf_sh[4][CHUNK];           // 4 KB
    __shared__ uint16_t t16_sh[4][CHUNK];          // 2 KB  (t*32)
    __shared__ float    sbuf[4][32][33];           // 16.9 KB

    const int b    = blockIdx.x;
    const int a    = b >> 5;
    const int rem  = b & 31;
    const int cg   = rem >> 2;          // colgroup 0..7 (32 cols each)
    const int cq   = rem & 3;           // chunkgroup 0..3
    const int tid  = threadIdx.x;
    const int w    = tid >> 5;
    const int lane = tid & 31;

    // stage tm column slice (input-only; overlaps chain via PDL)
    #pragma unroll
    for (int i = tid; i < NTASKS * 32; i += 128)
        tm_sh[i] = __ldg(tm + (i >> 5) * NTASKS + cg * 32 + (i & 31));
    __syncthreads();

    // zero output column 0 for this block's 32 columns (once per algo/cg)
    if (cq == 0 && tid < 32)
        out[(size_t)(a * NTASKS + cg * 32 + tid) * (size_t)(S_LEN + 1)] = 0.0f;

    const int q  = cq * 4 + w;          // this warp's chunk
    const int s0 = q * CHUNK;
    const int bq = a * NCHUNK + q;

    // wait for this chunk's chain, then consume one semaphore slot
    if (lane == 0) {
        int f;
        for (;;) {
            asm volatile("ld.global.acquire.gpu.s32 %0, [%1];"
                         : "=r"(f) : "l"(chain_done + bq) : "memory");
            if (f != 0) break;
            __nanosleep(100);
        }
        atomicAdd(chain_done + bq, -1);
    }
    __syncwarp();

    // stage (t, k) stream
    for (int i = lane; i < CHUNK; i += 32) {
        kf_sh[w][i]  = ldcgf(&k_glob[bq][i]);
        t16_sh[w][i] = (uint16_t)(__ldg(lx + s0 + i) << 5);
    }
    __syncwarp();

    const int   col = cg * 32 + lane;
    const float mem = memA[a];
    const float wh  = 0.5f * rcpf(__ldg(diff + col));

    float r = ldcgf(&seed_glob[bq][col]);   // seeded: no warm-up

    float* outw = out + (size_t)(a * NTASKS + cg * 32) * (size_t)(S_LEN + 1)
                + 1 + s0 + lane;

    #pragma unroll 1
    for (int tile = 0; tile < CHUNK / 32; tile++) {
        #pragma unroll
        for (int j = 0; j < 32; j++) {
            const int idx = tile * 32 + j;
            const float tv = tm_sh[(int)t16_sh[w][idx] + lane];
            r = fmaf(r, mem, tv * kf_sh[w][idx]);
            sbuf[w][lane][j] = tanhapx(r * wh);
        }
        __syncwarp();
        const float* sb = &sbuf[w][0][lane];
        float* op = outw + tile * 32;
        #pragma unroll
        for (int cl = 0; cl < 32; cl++) {
            __stcs(op, *sb);
            op += (S_LEN + 1);
            sb += 33;
        }
        __syncwarp();
    }
}

extern "C" void kernel_launch(void* const* d_in, const int* in_sizes, int n_in,
                              void* d_out, int out_size)
{
    (void)in_sizes; (void)n_in; (void)out_size;
    const int*   lx    = (const int*)  d_in[0];
    const float* tm    = (const float*)d_in[1];
    const float* diff  = (const float*)d_in[2];
    const float* eff   = (const float*)d_in[3];
    const float* mem   = (const float*)d_in[4];
    const float* boost = (const float*)d_in[5];
    float*       out   = (float*)d_out;

    idl_chain<<<NCHAINS / 2 / 4, 128>>>(lx, tm, diff, eff, mem, boost);

    // PDL: idl_out may start while idl_chain runs (sync via chain_done flags)
    {
        cudaLaunchConfig_t cfg = {};
        cfg.gridDim  = dim3(NALGOS * 32, 1, 1);
        cfg.blockDim = dim3(128, 1, 1);
        cfg.dynamicSmemBytes = 0;
        cfg.stream = 0;
        cudaLaunchAttribute attr[1];
        attr[0].id = cudaLaunchAttributeProgrammaticStreamSerialization;
        attr[0].val.programmaticStreamSerializationAllowed = 1;
        cfg.attrs = attr;
        cfg.numAttrs = 1;
        cudaLaunchKernelEx(&cfg, idl_out, lx, tm, diff, mem, out);
    }
}